// round 12
// baseline (speedup 1.0000x reference)
#include <cuda_runtime.h>
#include <math.h>

#define INF_V   100000000.0f
#define BG_ID_V 100000
#define RADIUS_V 1.5f
#define NGT 64
#define BLK 128

typedef unsigned long long u64;

// FPN level geometry (IMG=1024, strides 8..128); level offsets are multiples
// of 128, so every 128-thread block lies within exactly one level.
__constant__ int   c_off[5]    = {0, 16384, 20480, 21504, 21760};
__constant__ int   c_n[5]      = {128, 64, 32, 16, 8};
__constant__ float c_stride[5] = {8.f, 16.f, 32.f, 64.f, 128.f};
__constant__ float c_rstride[5]= {0.125f, 0.0625f, 0.03125f, 0.015625f, 0.0078125f};
__constant__ float c_lo[5]     = {-1.f, 64.f, 128.f, 256.f, 512.f};
__constant__ float c_hi[5]     = {64.f, 128.f, 256.f, 512.f, INF_V};

__device__ __forceinline__ float sqrt_approx(float v) {
    float r; asm("sqrt.approx.f32 %0,%1;" : "=f"(r) : "f"(v)); return r;
}

__global__ void __launch_bounds__(BLK)
fcos_fused_kernel(const float* __restrict__ loc,   // [L,2]
                  const float* __restrict__ gtb,   // [B,G,4]
                  const int*   __restrict__ gtc,   // [B,G]
                  float* __restrict__ out,
                  int L, int B)
{
    const int b  = blockIdx.y;
    const int i0 = blockIdx.x * BLK;         // first location of this block
    const int t  = threadIdx.x;

    // Level of this block (uniform branches)
    int lvl = 0;
    if (i0 >= 16384) lvl = 1;
    if (i0 >= 20480) lvl = 2;
    if (i0 >= 21504) lvl = 3;
    if (i0 >= 21760) lvl = 4;

    const float stride  = c_stride[lvl];
    const float rstride = c_rstride[lvl];    // exact reciprocal (pow2)
    const int   n       = c_n[lvl];
    const float rlo     = c_lo[lvl];
    const float rhi     = c_hi[lvl];

    // Block pixel bbox: spans whole rows [iy0, iy1] of the level grid.
    const int iy0 = (i0 - c_off[lvl]) / n;
    int iy1 = iy0 + (BLK > n ? (BLK / n) : 1) - 1;
    if (iy1 > n - 1) iy1 = n - 1;
    const float x_lo = 0.5f * stride;
    const float x_hi = ((float)n - 0.5f) * stride;
    const float y_lo = ((float)iy0 + 0.5f) * stride;
    const float y_hi = ((float)iy1 + 0.5f) * stride;

    // Prefetch this thread's location early (independent of cull phase).
    const int i = i0 + t;
    const bool active = (i < L);
    float x = 0.f, y = 0.f;
    if (active) {
        const float2 xy = ((const float2*)loc)[i];
        x = xy.x; y = xy.y;
    }

    __shared__ float4 sWin[NGT];    // compacted: candidate windows
    __shared__ float4 sBoxC[NGT];   // compacted: candidate boxes
    __shared__ u64    sKey[NGT];    // compacted: (area_bits << 32) | g
    __shared__ float4 sBoxG[NGT];   // uncompacted, indexed by g (epilogue)
    __shared__ int    sClsG[NGT];   // uncompacted, indexed by g (epilogue)
    __shared__ int    sCnt;
    __shared__ __align__(16) float sOut[BLK * 5];  // 16B-aligned for LDS.128

    if (t == 0) sCnt = 0;
    __syncthreads();

    // ---- cull & compact: threads 0..63 test one GT each ----
    if (t < NGT) {
        const float4 p = ((const float4*)gtb)[b * NGT + t];
        sBoxG[t] = p;                      // for epilogue (incl. bg -> g=0)
        sClsG[t] = gtc[b * NGT + t];

        const float cx = (p.x + p.z) * 0.5f;
        const float cy = (p.y + p.w) * 0.5f;
        const float s  = stride * RADIUS_V;
        // Exact reference formulas for the center-sampling window.
        const float xmin = fmaxf(cx - s, p.x);
        const float ymin = fmaxf(cy - s, p.y);
        const float xmax = fminf(cx + s, p.z);
        const float ymax = fminf(cy + s, p.w);

        // Size-range pre-cull (conservative, 1.0f FP margin):
        //   any loc inside window: max(w,h)/2 <= mx <= max(w,h)  (reals)
        const float w = p.z - p.x, h = p.w - p.y;
        const float md = fmaxf(w, h);
        const bool sz_ok = (md >= rlo - 1.0f) && (0.5f * md <= rhi + 1.0f);

        // Geometric overlap with block bbox (strict inside test implies it).
        if (sz_ok &&
            xmin < x_hi && xmax > x_lo && ymin < y_hi && ymax > y_lo) {
            const int pos = atomicAdd(&sCnt, 1);
            sWin[pos]  = make_float4(xmin, ymin, xmax, ymax);
            sBoxC[pos] = p;
            sKey[pos]  = ((u64)__float_as_uint((p.z - p.x) * (p.w - p.y)) << 32)
                         | (unsigned)t;
        }
    }
    __syncthreads();

    if (active) {
        // ---- branchless u64-min argmin over surviving candidates ----
        u64 bestkey = ~0ull;
        const int m = sCnt;
        #pragma unroll 2
        for (int c = 0; c < m; c++) {
            const float4 w = sWin[c];
            const float4 p = sBoxC[c];
            const float ins = fminf(fminf(x - w.x, w.z - x),
                                    fminf(y - w.y, w.w - y));
            const float l  = x - p.x;
            const float tt = y - p.y;
            const float r  = p.z - x;
            const float bv = p.w - y;
            const float mx = fmaxf(fmaxf(l, tt), fmaxf(r, bv));
            const u64 k = sKey[c];
            // u64 key order == (area, first gt idx): exact argmin semantics
            const bool ok = (ins > 0.0f) & (mx >= rlo) & (mx <= rhi) &
                            (k < bestkey);
            bestkey = ok ? k : bestkey;
        }

        // ---- epilogue ----
        const bool bg = (bestkey == ~0ull);
        const int  g  = bg ? 0 : (int)(bestkey & 0xffffffffu); // argmin(INF)=0
        const float4 p = sBoxG[g];
        const int label = bg ? BG_ID_V : sClsG[g];

        const float l  = x - p.x;
        const float tt = y - p.y;
        const float r  = p.z - x;
        const float bv = p.w - y;

        const float lrmin = fminf(l, r),   lrmax = fmaxf(l, r);
        const float tbmin = fminf(tt, bv), tbmax = fmaxf(tt, bv);
        // approx div/sqrt: ~1e-7 rel err on ctr only (gate is 1e-3)
        const float ratio = __fdividef(lrmin, lrmax) * __fdividef(tbmin, tbmax);
        const float ctr   = (ratio > 0.0f) ? sqrt_approx(ratio) : 0.0f;

        // stride is a power of two: multiply by reciprocal is bit-exact
        sOut[t * 5 + 0] = l  * rstride;   // t*5: gcd(5,32)=1 -> no conflicts
        sOut[t * 5 + 1] = tt * rstride;
        sOut[t * 5 + 2] = r  * rstride;
        sOut[t * 5 + 3] = bv * rstride;
        sOut[t * 5 + 4] = ctr;

        const size_t bl      = (size_t)b * L + i;
        const size_t off_lab = (size_t)B * L * 5;
        out[off_lab + bl]                 = (float)label;
        out[off_lab + (size_t)B * L + bl] = (float)g;
    }
    __syncthreads();

    // ---- coalesced float4 flush of the block's float_out region ----
    // (b*L + i0) is a multiple of 4 (L % 4 == 0, i0 % 128 == 0), so
    // (b*L+i0)*5 floats is 16B-aligned relative to the cudaMalloc'd base.
    const int nvalid = min(BLK, L - i0);
    const int total  = nvalid * 5;
    const int total4 = total >> 2;
    float* fdst = out + ((size_t)b * L + i0) * 5;
    float4* fdst4 = (float4*)fdst;
    const float4* s4 = (const float4*)sOut;
    for (int j = t; j < total4; j += BLK) fdst4[j] = s4[j];
    for (int j = (total4 << 2) + t; j < total; j += BLK) fdst[j] = sOut[j];
}

extern "C" void kernel_launch(void* const* d_in, const int* in_sizes, int n_in,
                              void* d_out, int out_size)
{
    const float* loc = (const float*)d_in[0];   // [L,2]
    const float* gtb = (const float*)d_in[3];   // [B,G,4]
    const int*   gtc = (const int*)  d_in[4];   // [B,G]

    const int L = in_sizes[2];
    const int B = in_sizes[4] / NGT;

    dim3 grid((L + BLK - 1) / BLK, B);
    fcos_fused_kernel<<<grid, BLK>>>(loc, gtb, gtc, (float*)d_out, L, B);
}